// round 9
// baseline (speedup 1.0000x reference)
#include <cuda_runtime.h>
#include <cuda_fp16.h>
#include <cstdint>
#include <cstddef>

// ---------------------------------------------------------------------------
// WindowAttention (Swin) on GB300 — Round 9.
//   - GEMMs: mma.sync fp16 2-term split (validated R8), now 3-stage cp.async.
//   - Attention: fp32, but exp() moved off MUFU onto the FMA pipe
//     (236M expf = 1.8ms of MUFU throughput was the R8 bottleneck).
//   - rel-pos bias gather precomputed once into g_bias.
// ---------------------------------------------------------------------------

#define NWIN      8192
#define NTOK      49
#define DIM       384
#define NHEAD     12
#define HEADD     32
#define NW_IMG    64
#define MROWS     (NWIN * NTOK)        // 401408
#define QKV_COLS  1152
#define K2        768                  // split K: hi | lo
#define SCALE_F   0.17677669529663687f

// Device scratch
__device__ float  g_qkv[(size_t)MROWS * QKV_COLS];
__device__ __half g_x2[(size_t)MROWS * K2];
__device__ __half g_attn2[(size_t)MROWS * K2];
__device__ __half g_wqkv2[(size_t)QKV_COLS * K2];
__device__ __half g_wproj2[(size_t)DIM * K2];
__device__ float  g_bias[NHEAD * NTOK * NTOK];   // [h][i][j]

// ---------------------------------------------------------------------------
// Helpers
// ---------------------------------------------------------------------------
__device__ __forceinline__ uint32_t smem_u32(const void* p) {
    uint32_t a;
    asm("{ .reg .u64 t; cvta.to.shared.u64 t, %1; cvt.u32.u64 %0, t; }"
        : "=r"(a) : "l"(p));
    return a;
}

__device__ __forceinline__ void cpa16(uint32_t dst, const void* src) {
    asm volatile("cp.async.cg.shared.global [%0], [%1], 16;"
                 :: "r"(dst), "l"(src));
}

__device__ __forceinline__ void ldsm_x4(uint32_t* r, uint32_t addr) {
    asm volatile("ldmatrix.sync.aligned.m8n8.x4.shared.b16 {%0,%1,%2,%3}, [%4];"
                 : "=r"(r[0]), "=r"(r[1]), "=r"(r[2]), "=r"(r[3])
                 : "r"(addr));
}

__device__ __forceinline__ void mma16816(float* d, const uint32_t* a,
                                         const uint32_t* b) {
    asm volatile(
        "mma.sync.aligned.m16n8k16.row.col.f32.f16.f16.f32 "
        "{%0,%1,%2,%3}, {%4,%5,%6,%7}, {%8,%9}, {%0,%1,%2,%3};"
        : "+f"(d[0]), "+f"(d[1]), "+f"(d[2]), "+f"(d[3])
        : "r"(a[0]), "r"(a[1]), "r"(a[2]), "r"(a[3]),
          "r"(b[0]), "r"(b[1]));
}

// exp(x) on the FMA pipe (no MUFU): 2^(x*log2e) with deg-5 Taylor for 2^f,
// f in [-0.5, 0.5]; max rel error ~2.4e-6. Valid for x in [-80, ~80].
__device__ __forceinline__ float fast_exp(float x) {
    float t = fmaxf(x, -80.0f) * 1.442695040888963f;
    float r = rintf(t);
    float f = t - r;
    float p =             1.3333558e-3f;
    p = fmaf(p, f, 9.6181291e-3f);
    p = fmaf(p, f, 5.5504109e-2f);
    p = fmaf(p, f, 2.4022651e-1f);
    p = fmaf(p, f, 6.9314718e-1f);
    p = fmaf(p, f, 1.0f);
    int ri = (int)r;
    return __int_as_float(__float_as_int(p) + ri * 8388608); // ri << 23
}

// ---------------------------------------------------------------------------
// Split kernels: fp32 [rows][384] -> fp16 [rows][768]
//   act layout: [hi | lo]   wgt layout: [hi | hi]
// ---------------------------------------------------------------------------
__global__ void split_act_kernel(const float* __restrict__ in,
                                 __half* __restrict__ out, long total4)
{
    long idx = (long)blockIdx.x * blockDim.x + threadIdx.x;
    if (idx >= total4) return;
    long r = idx / (DIM / 4);
    int  c4 = (int)(idx - r * (DIM / 4));
    float4 v = *((const float4*)(in + r * DIM) + c4);
    float a[4] = {v.x, v.y, v.z, v.w};
    __half hi[4], lo[4];
    #pragma unroll
    for (int i = 0; i < 4; i++) {
        hi[i] = __float2half_rn(a[i]);
        lo[i] = __float2half_rn(a[i] - __half2float(hi[i]));
    }
    __half2* s0 = (__half2*)(out + r * K2 + c4 * 4);
    __half2* s1 = (__half2*)(out + r * K2 + DIM + c4 * 4);
    s0[0] = __halves2half2(hi[0], hi[1]);
    s0[1] = __halves2half2(hi[2], hi[3]);
    s1[0] = __halves2half2(lo[0], lo[1]);
    s1[1] = __halves2half2(lo[2], lo[3]);
}

__global__ void split_wgt_kernel(const float* __restrict__ in,
                                 __half* __restrict__ out, long total4)
{
    long idx = (long)blockIdx.x * blockDim.x + threadIdx.x;
    if (idx >= total4) return;
    long r = idx / (DIM / 4);
    int  c4 = (int)(idx - r * (DIM / 4));
    float4 v = *((const float4*)(in + r * DIM) + c4);
    float a[4] = {v.x, v.y, v.z, v.w};
    __half hi[4];
    #pragma unroll
    for (int i = 0; i < 4; i++) hi[i] = __float2half_rn(a[i]);
    __half2 h0 = __halves2half2(hi[0], hi[1]);
    __half2 h1 = __halves2half2(hi[2], hi[3]);
    __half2* s0 = (__half2*)(out + r * K2 + c4 * 4);
    __half2* s1 = (__half2*)(out + r * K2 + DIM + c4 * 4);
    s0[0] = h0; s0[1] = h1;
    s1[0] = h0; s1[1] = h1;
}

// Precompute rel-pos bias: g_bias[h][i][j] = rel_table[rel_idx[i][j]*NHEAD+h]
__global__ void bias_prep_kernel(const float* __restrict__ rel_table,
                                 const int* __restrict__ rel_idx)
{
    int t = blockIdx.x * blockDim.x + threadIdx.x;
    if (t >= NHEAD * NTOK * NTOK) return;
    int h   = t / (NTOK * NTOK);
    int idx = t - h * (NTOK * NTOK);
    g_bias[t] = rel_table[rel_idx[idx] * NHEAD + h];
}

// ---------------------------------------------------------------------------
// HMMA GEMM: C[M][Nn] = A2[M][768] @ B2[Nn][768]^T + bias   (fp16 -> fp32)
// 128x128 tile, BK=64 (128B rows, XOR-8 swizzle), 3-stage cp.async,
// 8 warps (2x4), warp tile 64x32, mma.sync.m16n8k16.
// ---------------------------------------------------------------------------
#define BKC       64
#define NCH       (K2 / BKC)            // 12
#define TILE_BYTES 16384                // 128 rows x 128 bytes
#define STAGE_BYTES (2 * TILE_BYTES)    // A + B
#define NSTAGE    3
#define GSMEM     (NSTAGE * STAGE_BYTES + 128)

__global__ __launch_bounds__(256, 2)
void gemm_mma(const __half* __restrict__ A,
              const __half* __restrict__ B,
              const float* __restrict__ bias,
              float* __restrict__ C, int Nn)
{
    extern __shared__ uint8_t smem_raw[];
    const int tid  = threadIdx.x;
    const int warp = tid >> 5;
    const int lane = tid & 31;

    uint32_t sraw  = smem_u32(smem_raw);
    uint32_t sbase = (sraw + 127u) & ~127u;

    const int m0 = blockIdx.y << 7;
    const int n0 = blockIdx.x << 7;

    const char* Ag = (const char*)(A + (size_t)m0 * K2);
    const char* Bg = (const char*)(B + (size_t)n0 * K2);
    uint32_t sw[4];
    size_t   go[4];
    #pragma unroll
    for (int i = 0; i < 4; i++) {
        int u = i * 256 + tid;
        int r = u >> 3, c = u & 7;
        sw[i] = (uint32_t)(r * 128 + ((c ^ (r & 7)) << 4));
        go[i] = (size_t)r * (K2 * 2) + (size_t)c * 16;
    }

    auto load_chunk = [&](int c, int s) {
        uint32_t ab = sbase + s * STAGE_BYTES;
        uint32_t bb = ab + TILE_BYTES;
        size_t koff = (size_t)c * 128;
        #pragma unroll
        for (int i = 0; i < 4; i++) {
            cpa16(ab + sw[i], Ag + go[i] + koff);
            cpa16(bb + sw[i], Bg + go[i] + koff);
        }
        asm volatile("cp.async.commit_group;" ::: "memory");
    };

    const int wm = warp & 1;
    const int wn = warp >> 1;
    const int l15 = lane & 15;
    const int lhi = lane >> 4;
    const int g8  = lane >> 3;
    const int l8  = lane & 7;

    int rA[4], rowOffA[4];
    #pragma unroll
    for (int mf = 0; mf < 4; mf++) {
        rA[mf] = wm * 64 + mf * 16 + l15;
        rowOffA[mf] = rA[mf] * 128;
    }
    int rB[2], rowOffB[2];
    #pragma unroll
    for (int p = 0; p < 2; p++) {
        rB[p] = wn * 32 + p * 16 + (g8 >> 1) * 8 + l8;
        rowOffB[p] = rB[p] * 128;
    }

    float acc[4][4][4];
    #pragma unroll
    for (int mf = 0; mf < 4; mf++)
        #pragma unroll
        for (int nf = 0; nf < 4; nf++)
            #pragma unroll
            for (int e = 0; e < 4; e++) acc[mf][nf][e] = 0.0f;

    load_chunk(0, 0);
    load_chunk(1, 1);

    for (int c = 0; c < NCH; ++c) {
        if (c + 2 < NCH) {
            load_chunk(c + 2, (c + 2) % NSTAGE);
            asm volatile("cp.async.wait_group 2;" ::: "memory");
        } else if (c + 1 < NCH) {
            asm volatile("cp.async.wait_group 1;" ::: "memory");
        } else {
            asm volatile("cp.async.wait_group 0;" ::: "memory");
        }
        __syncthreads();

        const uint32_t aT = sbase + (c % NSTAGE) * STAGE_BYTES;
        const uint32_t bT = aT + TILE_BYTES;

        #pragma unroll
        for (int ks = 0; ks < 4; ++ks) {
            uint32_t af[4][4];
            #pragma unroll
            for (int mf = 0; mf < 4; mf++) {
                const int c16 = ks * 2 + lhi;
                ldsm_x4(af[mf], aT + rowOffA[mf] +
                                ((c16 ^ (rA[mf] & 7)) << 4));
            }
            uint32_t bf[2][4];
            #pragma unroll
            for (int p = 0; p < 2; p++) {
                const int c16 = ks * 2 + (g8 & 1);
                ldsm_x4(bf[p], bT + rowOffB[p] +
                               ((c16 ^ (rB[p] & 7)) << 4));
            }
            #pragma unroll
            for (int mf = 0; mf < 4; mf++) {
                mma16816(acc[mf][0], af[mf], &bf[0][0]);
                mma16816(acc[mf][1], af[mf], &bf[0][2]);
                mma16816(acc[mf][2], af[mf], &bf[1][0]);
                mma16816(acc[mf][3], af[mf], &bf[1][2]);
            }
        }
        __syncthreads();
    }

    const int colBase = n0 + wn * 32 + 2 * (lane & 3);
    float2 b2[4];
    #pragma unroll
    for (int nf = 0; nf < 4; nf++)
        b2[nf] = *(const float2*)(bias + colBase + nf * 8);

    const int rowBase = m0 + wm * 64 + (lane >> 2);
    #pragma unroll
    for (int mf = 0; mf < 4; mf++) {
        const int r0 = rowBase + mf * 16;
        #pragma unroll
        for (int nf = 0; nf < 4; nf++) {
            const int col = colBase + nf * 8;
            float2 v0 = make_float2(acc[mf][nf][0] + b2[nf].x,
                                    acc[mf][nf][1] + b2[nf].y);
            float2 v1 = make_float2(acc[mf][nf][2] + b2[nf].x,
                                    acc[mf][nf][3] + b2[nf].y);
            *(float2*)(C + (size_t)r0 * Nn + col)       = v0;
            *(float2*)(C + (size_t)(r0 + 8) * Nn + col) = v1;
        }
    }
}

// ---------------------------------------------------------------------------
// Fused attention kernel (fp32): grid (NWIN, NHEAD), 128 threads.
// exp on FMA pipe; bias pre-gathered; writes split fp16 into g_attn2.
// ---------------------------------------------------------------------------
__global__ __launch_bounds__(128)
void attn_kernel(const float* __restrict__ mask)
{
    __shared__ float q_s[NTOK][36];
    __shared__ float k_s[NTOK][36];
    __shared__ float v_s[NTOK][36];
    __shared__ float S[NTOK][53];   // S[j][i], odd stride -> conflict-free

    const int w   = blockIdx.x;
    const int h   = blockIdx.y;
    const int tid = threadIdx.x;

    const size_t base0 = (size_t)w * NTOK * QKV_COLS + h * HEADD;
    for (int idx = tid; idx < NTOK * HEADD; idx += 128) {
        const int i = idx >> 5, d = idx & 31;
        const size_t g = base0 + (size_t)i * QKV_COLS + d;
        q_s[i][d] = g_qkv[g] * SCALE_F;
        k_s[i][d] = g_qkv[g + 384];
        v_s[i][d] = g_qkv[g + 768];
    }

    const float* mrow = mask + (size_t)(w & (NW_IMG - 1)) * (NTOK * NTOK);
    const float* brow = g_bias + h * (NTOK * NTOK);
    for (int idx = tid; idx < NTOK * NTOK; idx += 128) {
        const int i = idx / NTOK;
        const int j = idx - i * NTOK;
        S[j][i] = brow[idx] + mrow[idx];
    }
    __syncthreads();

    {
        const int j  = tid & 63;
        const int ig = tid >> 6;
        if (j < NTOK) {
            float kreg[HEADD];
            #pragma unroll
            for (int kq = 0; kq < 8; ++kq)
                *(float4*)&kreg[kq * 4] = *(const float4*)&k_s[j][kq * 4];
            const int i0 = ig ? 25 : 0;
            const int i1 = ig ? NTOK : 25;
            for (int i = i0; i < i1; ++i) {
                float acc = 0.0f;
                #pragma unroll
                for (int kq = 0; kq < 8; ++kq) {
                    const float4 q4 = *(const float4*)&q_s[i][kq * 4];
                    acc += q4.x * kreg[kq * 4 + 0];
                    acc += q4.y * kreg[kq * 4 + 1];
                    acc += q4.z * kreg[kq * 4 + 2];
                    acc += q4.w * kreg[kq * 4 + 3];
                }
                S[j][i] += acc;
            }
        }
    }
    __syncthreads();

    if (tid < NTOK) {
        const int i = tid;
        float m = -1e30f;
        for (int j = 0; j < NTOK; ++j) m = fmaxf(m, S[j][i]);
        float sum = 0.0f;
        for (int j = 0; j < NTOK; ++j) {
            const float e = fast_exp(S[j][i] - m);
            S[j][i] = e;
            sum += e;
        }
        const float inv = 1.0f / sum;
        for (int j = 0; j < NTOK; ++j) S[j][i] *= inv;
    }
    __syncthreads();

    {
        const int d  = tid & 31;
        const int ig = tid >> 5;
        const int i0 = ig * 13;
        const int nrows = (i0 + 13 <= NTOK) ? 13 : (NTOK - i0);
        float o[13];
        #pragma unroll
        for (int r = 0; r < 13; ++r) o[r] = 0.0f;

        for (int j = 0; j < NTOK; ++j) {
            const float vj = v_s[j][d];
            #pragma unroll
            for (int r = 0; r < 13; ++r)
                if (r < nrows) o[r] += S[j][i0 + r] * vj;
        }
        for (int r = 0; r < nrows; ++r) {
            const size_t rowg = (size_t)(w * NTOK + i0 + r);
            const size_t base = rowg * K2 + h * HEADD + d;
            const float val = o[r];
            const __half hi = __float2half_rn(val);
            const __half lo = __float2half_rn(val - __half2float(hi));
            g_attn2[base]       = hi;
            g_attn2[base + DIM] = lo;
        }
    }
}

// ---------------------------------------------------------------------------
// Launch
// ---------------------------------------------------------------------------
extern "C" void kernel_launch(void* const* d_in, const int* in_sizes, int n_in,
                              void* d_out, int out_size)
{
    const float* x         = (const float*)d_in[0];
    const float* mask      = (const float*)d_in[1];
    const float* rel_table = (const float*)d_in[2];
    const float* qkv_w     = (const float*)d_in[3];
    const float* qkv_b     = (const float*)d_in[4];
    const float* proj_w    = (const float*)d_in[5];
    const float* proj_b    = (const float*)d_in[6];
    const int*   rel_idx   = (const int*)d_in[7];
    float*       out       = (float*)d_out;

    void *qkv_p, *x2_p, *attn2_p, *wq2_p, *wp2_p;
    cudaGetSymbolAddress(&qkv_p,   g_qkv);
    cudaGetSymbolAddress(&x2_p,    g_x2);
    cudaGetSymbolAddress(&attn2_p, g_attn2);
    cudaGetSymbolAddress(&wq2_p,   g_wqkv2);
    cudaGetSymbolAddress(&wp2_p,   g_wproj2);

    cudaFuncSetAttribute(gemm_mma,
                         cudaFuncAttributeMaxDynamicSharedMemorySize, GSMEM);

    // Splits + bias precompute
    {
        long t4 = (long)MROWS * (DIM / 4);
        split_act_kernel<<<(unsigned)((t4 + 255) / 256), 256>>>(
            x, (__half*)x2_p, t4);
    }
    {
        long t4 = (long)QKV_COLS * (DIM / 4);
        split_wgt_kernel<<<(unsigned)((t4 + 255) / 256), 256>>>(
            qkv_w, (__half*)wq2_p, t4);
    }
    {
        long t4 = (long)DIM * (DIM / 4);
        split_wgt_kernel<<<(unsigned)((t4 + 255) / 256), 256>>>(
            proj_w, (__half*)wp2_p, t4);
    }
    {
        int tot = NHEAD * NTOK * NTOK;
        bias_prep_kernel<<<(tot + 255) / 256, 256>>>(rel_table, rel_idx);
    }

    // 1) QKV GEMM (HMMA fp16)
    {
        dim3 grid(QKV_COLS / 128, MROWS / 128);    // (9, 3136)
        gemm_mma<<<grid, 256, GSMEM>>>(
            (const __half*)x2_p, (const __half*)wq2_p,
            qkv_b, (float*)qkv_p, QKV_COLS);
    }

    // 2) Fused attention
    {
        dim3 grid(NWIN, NHEAD);
        attn_kernel<<<grid, 128>>>(mask);
    }

    // 3) Output projection GEMM (HMMA fp16)
    {
        dim3 grid(DIM / 128, MROWS / 128);         // (3, 3136)
        gemm_mma<<<grid, 256, GSMEM>>>(
            (const __half*)attn2_p, (const __half*)wp2_p,
            proj_b, out, DIM);
    }
}

// round 10
// speedup vs baseline: 1.5556x; 1.5556x over previous
#include <cuda_runtime.h>
#include <cuda_fp16.h>
#include <cstdint>
#include <cstddef>

// ---------------------------------------------------------------------------
// WindowAttention (Swin) on GB300 — Round 10.
// Controlled experiment: GEMM reverted to the R8 2-stage config (proven fast);
// attention keeps R9's fast_exp (FMA-pipe exp), pre-gathered bias, stride-53 S.
// ---------------------------------------------------------------------------

#define NWIN      8192
#define NTOK      49
#define DIM       384
#define NHEAD     12
#define HEADD     32
#define NW_IMG    64
#define MROWS     (NWIN * NTOK)        // 401408
#define QKV_COLS  1152
#define K2        768                  // split K: hi | lo
#define SCALE_F   0.17677669529663687f

// Device scratch
__device__ float  g_qkv[(size_t)MROWS * QKV_COLS];
__device__ __half g_x2[(size_t)MROWS * K2];
__device__ __half g_attn2[(size_t)MROWS * K2];
__device__ __half g_wqkv2[(size_t)QKV_COLS * K2];
__device__ __half g_wproj2[(size_t)DIM * K2];
__device__ float  g_bias[NHEAD * NTOK * NTOK];   // [h][i][j]

// ---------------------------------------------------------------------------
// Helpers
// ---------------------------------------------------------------------------
__device__ __forceinline__ uint32_t smem_u32(const void* p) {
    uint32_t a;
    asm("{ .reg .u64 t; cvta.to.shared.u64 t, %1; cvt.u32.u64 %0, t; }"
        : "=r"(a) : "l"(p));
    return a;
}

__device__ __forceinline__ void cpa16(uint32_t dst, const void* src) {
    asm volatile("cp.async.cg.shared.global [%0], [%1], 16;"
                 :: "r"(dst), "l"(src));
}

__device__ __forceinline__ void ldsm_x4(uint32_t* r, uint32_t addr) {
    asm volatile("ldmatrix.sync.aligned.m8n8.x4.shared.b16 {%0,%1,%2,%3}, [%4];"
                 : "=r"(r[0]), "=r"(r[1]), "=r"(r[2]), "=r"(r[3])
                 : "r"(addr));
}

__device__ __forceinline__ void mma16816(float* d, const uint32_t* a,
                                         const uint32_t* b) {
    asm volatile(
        "mma.sync.aligned.m16n8k16.row.col.f32.f16.f16.f32 "
        "{%0,%1,%2,%3}, {%4,%5,%6,%7}, {%8,%9}, {%0,%1,%2,%3};"
        : "+f"(d[0]), "+f"(d[1]), "+f"(d[2]), "+f"(d[3])
        : "r"(a[0]), "r"(a[1]), "r"(a[2]), "r"(a[3]),
          "r"(b[0]), "r"(b[1]));
}

// exp(x) on the FMA pipe (no MUFU): 2^(x*log2e) with deg-5 poly for 2^f,
// f in [-0.5, 0.5]; max rel error ~2.4e-6. Valid for x in [-80, ~80].
__device__ __forceinline__ float fast_exp(float x) {
    float t = fmaxf(x, -80.0f) * 1.442695040888963f;
    float r = rintf(t);
    float f = t - r;
    float p =             1.3333558e-3f;
    p = fmaf(p, f, 9.6181291e-3f);
    p = fmaf(p, f, 5.5504109e-2f);
    p = fmaf(p, f, 2.4022651e-1f);
    p = fmaf(p, f, 6.9314718e-1f);
    p = fmaf(p, f, 1.0f);
    int ri = (int)r;
    return __int_as_float(__float_as_int(p) + ri * 8388608); // ri << 23
}

// ---------------------------------------------------------------------------
// Split kernels: fp32 [rows][384] -> fp16 [rows][768]
//   act layout: [hi | lo]   wgt layout: [hi | hi]
// ---------------------------------------------------------------------------
__global__ void split_act_kernel(const float* __restrict__ in,
                                 __half* __restrict__ out, long total4)
{
    long idx = (long)blockIdx.x * blockDim.x + threadIdx.x;
    if (idx >= total4) return;
    long r = idx / (DIM / 4);
    int  c4 = (int)(idx - r * (DIM / 4));
    float4 v = *((const float4*)(in + r * DIM) + c4);
    float a[4] = {v.x, v.y, v.z, v.w};
    __half hi[4], lo[4];
    #pragma unroll
    for (int i = 0; i < 4; i++) {
        hi[i] = __float2half_rn(a[i]);
        lo[i] = __float2half_rn(a[i] - __half2float(hi[i]));
    }
    __half2* s0 = (__half2*)(out + r * K2 + c4 * 4);
    __half2* s1 = (__half2*)(out + r * K2 + DIM + c4 * 4);
    s0[0] = __halves2half2(hi[0], hi[1]);
    s0[1] = __halves2half2(hi[2], hi[3]);
    s1[0] = __halves2half2(lo[0], lo[1]);
    s1[1] = __halves2half2(lo[2], lo[3]);
}

__global__ void split_wgt_kernel(const float* __restrict__ in,
                                 __half* __restrict__ out, long total4)
{
    long idx = (long)blockIdx.x * blockDim.x + threadIdx.x;
    if (idx >= total4) return;
    long r = idx / (DIM / 4);
    int  c4 = (int)(idx - r * (DIM / 4));
    float4 v = *((const float4*)(in + r * DIM) + c4);
    float a[4] = {v.x, v.y, v.z, v.w};
    __half hi[4];
    #pragma unroll
    for (int i = 0; i < 4; i++) hi[i] = __float2half_rn(a[i]);
    __half2 h0 = __halves2half2(hi[0], hi[1]);
    __half2 h1 = __halves2half2(hi[2], hi[3]);
    __half2* s0 = (__half2*)(out + r * K2 + c4 * 4);
    __half2* s1 = (__half2*)(out + r * K2 + DIM + c4 * 4);
    s0[0] = h0; s0[1] = h1;
    s1[0] = h0; s1[1] = h1;
}

// Precompute rel-pos bias: g_bias[h][i][j] = rel_table[rel_idx[i][j]*NHEAD+h]
__global__ void bias_prep_kernel(const float* __restrict__ rel_table,
                                 const int* __restrict__ rel_idx)
{
    int t = blockIdx.x * blockDim.x + threadIdx.x;
    if (t >= NHEAD * NTOK * NTOK) return;
    int h   = t / (NTOK * NTOK);
    int idx = t - h * (NTOK * NTOK);
    g_bias[t] = rel_table[rel_idx[idx] * NHEAD + h];
}

// ---------------------------------------------------------------------------
// HMMA GEMM (R8 config, verbatim): C = A2 @ B2^T + bias  (fp16 -> fp32)
// 128x128 tile, BK=64 (128B rows, XOR-8 swizzle), 2-stage cp.async,
// 8 warps (2x4), warp tile 64x32, mma.sync.m16n8k16.
// ---------------------------------------------------------------------------
#define BKC       64
#define NCH       (K2 / BKC)            // 12
#define TILE_BYTES 16384                // 128 rows x 128 bytes
#define STAGE_BYTES (2 * TILE_BYTES)    // A + B
#define GSMEM     (2 * STAGE_BYTES + 128)

__global__ __launch_bounds__(256, 2)
void gemm_mma(const __half* __restrict__ A,
              const __half* __restrict__ B,
              const float* __restrict__ bias,
              float* __restrict__ C, int Nn)
{
    extern __shared__ uint8_t smem_raw[];
    const int tid  = threadIdx.x;
    const int warp = tid >> 5;
    const int lane = tid & 31;

    uint32_t sraw  = smem_u32(smem_raw);
    uint32_t sbase = (sraw + 127u) & ~127u;   // 128B align

    const int m0 = blockIdx.y << 7;
    const int n0 = blockIdx.x << 7;

    const char* Ag = (const char*)(A + (size_t)m0 * K2);
    const char* Bg = (const char*)(B + (size_t)n0 * K2);
    uint32_t sw[4];
    size_t   go[4];
    #pragma unroll
    for (int i = 0; i < 4; i++) {
        int u = i * 256 + tid;
        int r = u >> 3, c = u & 7;
        sw[i] = (uint32_t)(r * 128 + ((c ^ (r & 7)) << 4));
        go[i] = (size_t)r * (K2 * 2) + (size_t)c * 16;
    }

    auto load_chunk = [&](int c, int s) {
        uint32_t ab = sbase + s * STAGE_BYTES;
        uint32_t bb = ab + TILE_BYTES;
        size_t koff = (size_t)c * 128;    // 64 fp16 = 128 bytes
        #pragma unroll
        for (int i = 0; i < 4; i++) {
            cpa16(ab + sw[i], Ag + go[i] + koff);
            cpa16(bb + sw[i], Bg + go[i] + koff);
        }
        asm volatile("cp.async.commit_group;" ::: "memory");
    };

    const int wm = warp & 1;          // m offset 0/64
    const int wn = warp >> 1;         // n offset 0/32/64/96
    const int l15 = lane & 15;
    const int lhi = lane >> 4;        // k-half for A ldmatrix
    const int g8  = lane >> 3;        // matrix id for B ldmatrix
    const int l8  = lane & 7;

    int rA[4], rowOffA[4];
    #pragma unroll
    for (int mf = 0; mf < 4; mf++) {
        rA[mf] = wm * 64 + mf * 16 + l15;
        rowOffA[mf] = rA[mf] * 128;
    }
    int rB[2], rowOffB[2];
    #pragma unroll
    for (int p = 0; p < 2; p++) {
        rB[p] = wn * 32 + p * 16 + (g8 >> 1) * 8 + l8;
        rowOffB[p] = rB[p] * 128;
    }

    float acc[4][4][4];
    #pragma unroll
    for (int mf = 0; mf < 4; mf++)
        #pragma unroll
        for (int nf = 0; nf < 4; nf++)
            #pragma unroll
            for (int e = 0; e < 4; e++) acc[mf][nf][e] = 0.0f;

    load_chunk(0, 0);

    for (int c = 0; c < NCH; ++c) {
        if (c + 1 < NCH) {
            load_chunk(c + 1, (c + 1) & 1);
            asm volatile("cp.async.wait_group 1;" ::: "memory");
        } else {
            asm volatile("cp.async.wait_group 0;" ::: "memory");
        }
        __syncthreads();

        const uint32_t aT = sbase + (c & 1) * STAGE_BYTES;
        const uint32_t bT = aT + TILE_BYTES;

        #pragma unroll
        for (int ks = 0; ks < 4; ++ks) {
            uint32_t af[4][4];
            #pragma unroll
            for (int mf = 0; mf < 4; mf++) {
                const int c16 = ks * 2 + lhi;
                ldsm_x4(af[mf], aT + rowOffA[mf] +
                                ((c16 ^ (rA[mf] & 7)) << 4));
            }
            uint32_t bf[2][4];
            #pragma unroll
            for (int p = 0; p < 2; p++) {
                const int c16 = ks * 2 + (g8 & 1);
                ldsm_x4(bf[p], bT + rowOffB[p] +
                               ((c16 ^ (rB[p] & 7)) << 4));
            }
            #pragma unroll
            for (int mf = 0; mf < 4; mf++) {
                mma16816(acc[mf][0], af[mf], &bf[0][0]);
                mma16816(acc[mf][1], af[mf], &bf[0][2]);
                mma16816(acc[mf][2], af[mf], &bf[1][0]);
                mma16816(acc[mf][3], af[mf], &bf[1][2]);
            }
        }
        __syncthreads();
    }

    const int colBase = n0 + wn * 32 + 2 * (lane & 3);
    float2 b2[4];
    #pragma unroll
    for (int nf = 0; nf < 4; nf++)
        b2[nf] = *(const float2*)(bias + colBase + nf * 8);

    const int rowBase = m0 + wm * 64 + (lane >> 2);
    #pragma unroll
    for (int mf = 0; mf < 4; mf++) {
        const int r0 = rowBase + mf * 16;
        #pragma unroll
        for (int nf = 0; nf < 4; nf++) {
            const int col = colBase + nf * 8;
            float2 v0 = make_float2(acc[mf][nf][0] + b2[nf].x,
                                    acc[mf][nf][1] + b2[nf].y);
            float2 v1 = make_float2(acc[mf][nf][2] + b2[nf].x,
                                    acc[mf][nf][3] + b2[nf].y);
            *(float2*)(C + (size_t)r0 * Nn + col)       = v0;
            *(float2*)(C + (size_t)(r0 + 8) * Nn + col) = v1;
        }
    }
}

// ---------------------------------------------------------------------------
// Fused attention kernel (fp32): grid (NWIN, NHEAD), 128 threads.
// exp on FMA pipe; bias pre-gathered; writes split fp16 into g_attn2.
// ---------------------------------------------------------------------------
__global__ __launch_bounds__(128)
void attn_kernel(const float* __restrict__ mask)
{
    __shared__ float q_s[NTOK][36];
    __shared__ float k_s[NTOK][36];
    __shared__ float v_s[NTOK][36];
    __shared__ float S[NTOK][53];   // S[j][i], odd stride -> conflict-free

    const int w   = blockIdx.x;
    const int h   = blockIdx.y;
    const int tid = threadIdx.x;

    const size_t base0 = (size_t)w * NTOK * QKV_COLS + h * HEADD;
    for (int idx = tid; idx < NTOK * HEADD; idx += 128) {
        const int i = idx >> 5, d = idx & 31;
        const size_t g = base0 + (size_t)i * QKV_COLS + d;
        q_s[i][d] = g_qkv[g] * SCALE_F;
        k_s[i][d] = g_qkv[g + 384];
        v_s[i][d] = g_qkv[g + 768];
    }

    const float* mrow = mask + (size_t)(w & (NW_IMG - 1)) * (NTOK * NTOK);
    const float* brow = g_bias + h * (NTOK * NTOK);
    for (int idx = tid; idx < NTOK * NTOK; idx += 128) {
        const int i = idx / NTOK;
        const int j = idx - i * NTOK;
        S[j][i] = brow[idx] + mrow[idx];
    }
    __syncthreads();

    {
        const int j  = tid & 63;
        const int ig = tid >> 6;
        if (j < NTOK) {
            float kreg[HEADD];
            #pragma unroll
            for (int kq = 0; kq < 8; ++kq)
                *(float4*)&kreg[kq * 4] = *(const float4*)&k_s[j][kq * 4];
            const int i0 = ig ? 25 : 0;
            const int i1 = ig ? NTOK : 25;
            for (int i = i0; i < i1; ++i) {
                float acc = 0.0f;
                #pragma unroll
                for (int kq = 0; kq < 8; ++kq) {
                    const float4 q4 = *(const float4*)&q_s[i][kq * 4];
                    acc += q4.x * kreg[kq * 4 + 0];
                    acc += q4.y * kreg[kq * 4 + 1];
                    acc += q4.z * kreg[kq * 4 + 2];
                    acc += q4.w * kreg[kq * 4 + 3];
                }
                S[j][i] += acc;
            }
        }
    }
    __syncthreads();

    if (tid < NTOK) {
        const int i = tid;
        float m = -1e30f;
        for (int j = 0; j < NTOK; ++j) m = fmaxf(m, S[j][i]);
        float sum = 0.0f;
        for (int j = 0; j < NTOK; ++j) {
            const float e = fast_exp(S[j][i] - m);
            S[j][i] = e;
            sum += e;
        }
        const float inv = 1.0f / sum;
        for (int j = 0; j < NTOK; ++j) S[j][i] *= inv;
    }
    __syncthreads();

    {
        const int d  = tid & 31;
        const int ig = tid >> 5;
        const int i0 = ig * 13;
        const int nrows = (i0 + 13 <= NTOK) ? 13 : (NTOK - i0);
        float o[13];
        #pragma unroll
        for (int r = 0; r < 13; ++r) o[r] = 0.0f;

        for (int j = 0; j < NTOK; ++j) {
            const float vj = v_s[j][d];
            #pragma unroll
            for (int r = 0; r < 13; ++r)
                if (r < nrows) o[r] += S[j][i0 + r] * vj;
        }
        for (int r = 0; r < nrows; ++r) {
            const size_t rowg = (size_t)(w * NTOK + i0 + r);
            const size_t base = rowg * K2 + h * HEADD + d;
            const float val = o[r];
            const __half hi = __float2half_rn(val);
            const __half lo = __float2half_rn(val - __half2float(hi));
            g_attn2[base]       = hi;
            g_attn2[base + DIM] = lo;
        }
    }
}

// ---------------------------------------------------------------------------
// Launch
// ---------------------------------------------------------------------------
extern "C" void kernel_launch(void* const* d_in, const int* in_sizes, int n_in,
                              void* d_out, int out_size)
{
    const float* x         = (const float*)d_in[0];
    const float* mask      = (const float*)d_in[1];
    const float* rel_table = (const float*)d_in[2];
    const float* qkv_w     = (const float*)d_in[3];
    const float* qkv_b     = (const float*)d_in[4];
    const float* proj_w    = (const float*)d_in[5];
    const float* proj_b    = (const float*)d_in[6];
    const int*   rel_idx   = (const int*)d_in[7];
    float*       out       = (float*)d_out;

    void *qkv_p, *x2_p, *attn2_p, *wq2_p, *wp2_p;
    cudaGetSymbolAddress(&qkv_p,   g_qkv);
    cudaGetSymbolAddress(&x2_p,    g_x2);
    cudaGetSymbolAddress(&attn2_p, g_attn2);
    cudaGetSymbolAddress(&wq2_p,   g_wqkv2);
    cudaGetSymbolAddress(&wp2_p,   g_wproj2);

    cudaFuncSetAttribute(gemm_mma,
                         cudaFuncAttributeMaxDynamicSharedMemorySize, GSMEM);

    // Splits + bias precompute
    {
        long t4 = (long)MROWS * (DIM / 4);
        split_act_kernel<<<(unsigned)((t4 + 255) / 256), 256>>>(
            x, (__half*)x2_p, t4);
    }
    {
        long t4 = (long)QKV_COLS * (DIM / 4);
        split_wgt_kernel<<<(unsigned)((t4 + 255) / 256), 256>>>(
            qkv_w, (__half*)wq2_p, t4);
    }
    {
        long t4 = (long)DIM * (DIM / 4);
        split_wgt_kernel<<<(unsigned)((t4 + 255) / 256), 256>>>(
            proj_w, (__half*)wp2_p, t4);
    }
    {
        int tot = NHEAD * NTOK * NTOK;
        bias_prep_kernel<<<(tot + 255) / 256, 256>>>(rel_table, rel_idx);
    }

    // 1) QKV GEMM (HMMA fp16)
    {
        dim3 grid(QKV_COLS / 128, MROWS / 128);    // (9, 3136)
        gemm_mma<<<grid, 256, GSMEM>>>(
            (const __half*)x2_p, (const __half*)wq2_p,
            qkv_b, (float*)qkv_p, QKV_COLS);
    }

    // 2) Fused attention
    {
        dim3 grid(NWIN, NHEAD);
        attn_kernel<<<grid, 128>>>(mask);
    }

    // 3) Output projection GEMM (HMMA fp16)
    {
        dim3 grid(DIM / 128, MROWS / 128);         // (3, 3136)
        gemm_mma<<<grid, 256, GSMEM>>>(
            (const __half*)attn2_p, (const __half*)wp2_p,
            proj_b, out, DIM);
    }
}

// round 11
// speedup vs baseline: 1.5981x; 1.0273x over previous
#include <cuda_runtime.h>
#include <cuda_fp16.h>
#include <cstdint>
#include <cstddef>

// ---------------------------------------------------------------------------
// WindowAttention (Swin) on GB300 — Round 11.
// GEMMs: R8/R10 config verbatim (2-stage, proven). Attention: break fp32
// dependency chains (4-way ILP in QK dot products and softmax reductions).
// ---------------------------------------------------------------------------

#define NWIN      8192
#define NTOK      49
#define DIM       384
#define NHEAD     12
#define HEADD     32
#define NW_IMG    64
#define MROWS     (NWIN * NTOK)        // 401408
#define QKV_COLS  1152
#define K2        768                  // split K: hi | lo
#define SCALE_F   0.17677669529663687f

// Device scratch
__device__ float  g_qkv[(size_t)MROWS * QKV_COLS];
__device__ __half g_x2[(size_t)MROWS * K2];
__device__ __half g_attn2[(size_t)MROWS * K2];
__device__ __half g_wqkv2[(size_t)QKV_COLS * K2];
__device__ __half g_wproj2[(size_t)DIM * K2];
__device__ float  g_bias[NHEAD * NTOK * NTOK];   // [h][i][j]

// ---------------------------------------------------------------------------
// Helpers
// ---------------------------------------------------------------------------
__device__ __forceinline__ uint32_t smem_u32(const void* p) {
    uint32_t a;
    asm("{ .reg .u64 t; cvta.to.shared.u64 t, %1; cvt.u32.u64 %0, t; }"
        : "=r"(a) : "l"(p));
    return a;
}

__device__ __forceinline__ void cpa16(uint32_t dst, const void* src) {
    asm volatile("cp.async.cg.shared.global [%0], [%1], 16;"
                 :: "r"(dst), "l"(src));
}

__device__ __forceinline__ void ldsm_x4(uint32_t* r, uint32_t addr) {
    asm volatile("ldmatrix.sync.aligned.m8n8.x4.shared.b16 {%0,%1,%2,%3}, [%4];"
                 : "=r"(r[0]), "=r"(r[1]), "=r"(r[2]), "=r"(r[3])
                 : "r"(addr));
}

__device__ __forceinline__ void mma16816(float* d, const uint32_t* a,
                                         const uint32_t* b) {
    asm volatile(
        "mma.sync.aligned.m16n8k16.row.col.f32.f16.f16.f32 "
        "{%0,%1,%2,%3}, {%4,%5,%6,%7}, {%8,%9}, {%0,%1,%2,%3};"
        : "+f"(d[0]), "+f"(d[1]), "+f"(d[2]), "+f"(d[3])
        : "r"(a[0]), "r"(a[1]), "r"(a[2]), "r"(a[3]),
          "r"(b[0]), "r"(b[1]));
}

// exp(x) on the FMA pipe (no MUFU): 2^(x*log2e), deg-5 poly, rel err ~2.4e-6.
__device__ __forceinline__ float fast_exp(float x) {
    float t = fmaxf(x, -80.0f) * 1.442695040888963f;
    float r = rintf(t);
    float f = t - r;
    float p =             1.3333558e-3f;
    p = fmaf(p, f, 9.6181291e-3f);
    p = fmaf(p, f, 5.5504109e-2f);
    p = fmaf(p, f, 2.4022651e-1f);
    p = fmaf(p, f, 6.9314718e-1f);
    p = fmaf(p, f, 1.0f);
    int ri = (int)r;
    return __int_as_float(__float_as_int(p) + ri * 8388608); // ri << 23
}

// ---------------------------------------------------------------------------
// Split kernels: fp32 [rows][384] -> fp16 [rows][768]
// ---------------------------------------------------------------------------
__global__ void split_act_kernel(const float* __restrict__ in,
                                 __half* __restrict__ out, long total4)
{
    long idx = (long)blockIdx.x * blockDim.x + threadIdx.x;
    if (idx >= total4) return;
    long r = idx / (DIM / 4);
    int  c4 = (int)(idx - r * (DIM / 4));
    float4 v = *((const float4*)(in + r * DIM) + c4);
    float a[4] = {v.x, v.y, v.z, v.w};
    __half hi[4], lo[4];
    #pragma unroll
    for (int i = 0; i < 4; i++) {
        hi[i] = __float2half_rn(a[i]);
        lo[i] = __float2half_rn(a[i] - __half2float(hi[i]));
    }
    __half2* s0 = (__half2*)(out + r * K2 + c4 * 4);
    __half2* s1 = (__half2*)(out + r * K2 + DIM + c4 * 4);
    s0[0] = __halves2half2(hi[0], hi[1]);
    s0[1] = __halves2half2(hi[2], hi[3]);
    s1[0] = __halves2half2(lo[0], lo[1]);
    s1[1] = __halves2half2(lo[2], lo[3]);
}

__global__ void split_wgt_kernel(const float* __restrict__ in,
                                 __half* __restrict__ out, long total4)
{
    long idx = (long)blockIdx.x * blockDim.x + threadIdx.x;
    if (idx >= total4) return;
    long r = idx / (DIM / 4);
    int  c4 = (int)(idx - r * (DIM / 4));
    float4 v = *((const float4*)(in + r * DIM) + c4);
    float a[4] = {v.x, v.y, v.z, v.w};
    __half hi[4];
    #pragma unroll
    for (int i = 0; i < 4; i++) hi[i] = __float2half_rn(a[i]);
    __half2 h0 = __halves2half2(hi[0], hi[1]);
    __half2 h1 = __halves2half2(hi[2], hi[3]);
    __half2* s0 = (__half2*)(out + r * K2 + c4 * 4);
    __half2* s1 = (__half2*)(out + r * K2 + DIM + c4 * 4);
    s0[0] = h0; s0[1] = h1;
    s1[0] = h0; s1[1] = h1;
}

__global__ void bias_prep_kernel(const float* __restrict__ rel_table,
                                 const int* __restrict__ rel_idx)
{
    int t = blockIdx.x * blockDim.x + threadIdx.x;
    if (t >= NHEAD * NTOK * NTOK) return;
    int h   = t / (NTOK * NTOK);
    int idx = t - h * (NTOK * NTOK);
    g_bias[t] = rel_table[rel_idx[idx] * NHEAD + h];
}

// ---------------------------------------------------------------------------
// HMMA GEMM (R8 config, verbatim): C = A2 @ B2^T + bias  (fp16 -> fp32)
// ---------------------------------------------------------------------------
#define BKC       64
#define NCH       (K2 / BKC)            // 12
#define TILE_BYTES 16384
#define STAGE_BYTES (2 * TILE_BYTES)
#define GSMEM     (2 * STAGE_BYTES + 128)

__global__ __launch_bounds__(256, 2)
void gemm_mma(const __half* __restrict__ A,
              const __half* __restrict__ B,
              const float* __restrict__ bias,
              float* __restrict__ C, int Nn)
{
    extern __shared__ uint8_t smem_raw[];
    const int tid  = threadIdx.x;
    const int warp = tid >> 5;
    const int lane = tid & 31;

    uint32_t sraw  = smem_u32(smem_raw);
    uint32_t sbase = (sraw + 127u) & ~127u;

    const int m0 = blockIdx.y << 7;
    const int n0 = blockIdx.x << 7;

    const char* Ag = (const char*)(A + (size_t)m0 * K2);
    const char* Bg = (const char*)(B + (size_t)n0 * K2);
    uint32_t sw[4];
    size_t   go[4];
    #pragma unroll
    for (int i = 0; i < 4; i++) {
        int u = i * 256 + tid;
        int r = u >> 3, c = u & 7;
        sw[i] = (uint32_t)(r * 128 + ((c ^ (r & 7)) << 4));
        go[i] = (size_t)r * (K2 * 2) + (size_t)c * 16;
    }

    auto load_chunk = [&](int c, int s) {
        uint32_t ab = sbase + s * STAGE_BYTES;
        uint32_t bb = ab + TILE_BYTES;
        size_t koff = (size_t)c * 128;
        #pragma unroll
        for (int i = 0; i < 4; i++) {
            cpa16(ab + sw[i], Ag + go[i] + koff);
            cpa16(bb + sw[i], Bg + go[i] + koff);
        }
        asm volatile("cp.async.commit_group;" ::: "memory");
    };

    const int wm = warp & 1;
    const int wn = warp >> 1;
    const int l15 = lane & 15;
    const int lhi = lane >> 4;
    const int g8  = lane >> 3;
    const int l8  = lane & 7;

    int rA[4], rowOffA[4];
    #pragma unroll
    for (int mf = 0; mf < 4; mf++) {
        rA[mf] = wm * 64 + mf * 16 + l15;
        rowOffA[mf] = rA[mf] * 128;
    }
    int rB[2], rowOffB[2];
    #pragma unroll
    for (int p = 0; p < 2; p++) {
        rB[p] = wn * 32 + p * 16 + (g8 >> 1) * 8 + l8;
        rowOffB[p] = rB[p] * 128;
    }

    float acc[4][4][4];
    #pragma unroll
    for (int mf = 0; mf < 4; mf++)
        #pragma unroll
        for (int nf = 0; nf < 4; nf++)
            #pragma unroll
            for (int e = 0; e < 4; e++) acc[mf][nf][e] = 0.0f;

    load_chunk(0, 0);

    for (int c = 0; c < NCH; ++c) {
        if (c + 1 < NCH) {
            load_chunk(c + 1, (c + 1) & 1);
            asm volatile("cp.async.wait_group 1;" ::: "memory");
        } else {
            asm volatile("cp.async.wait_group 0;" ::: "memory");
        }
        __syncthreads();

        const uint32_t aT = sbase + (c & 1) * STAGE_BYTES;
        const uint32_t bT = aT + TILE_BYTES;

        #pragma unroll
        for (int ks = 0; ks < 4; ++ks) {
            uint32_t af[4][4];
            #pragma unroll
            for (int mf = 0; mf < 4; mf++) {
                const int c16 = ks * 2 + lhi;
                ldsm_x4(af[mf], aT + rowOffA[mf] +
                                ((c16 ^ (rA[mf] & 7)) << 4));
            }
            uint32_t bf[2][4];
            #pragma unroll
            for (int p = 0; p < 2; p++) {
                const int c16 = ks * 2 + (g8 & 1);
                ldsm_x4(bf[p], bT + rowOffB[p] +
                               ((c16 ^ (rB[p] & 7)) << 4));
            }
            #pragma unroll
            for (int mf = 0; mf < 4; mf++) {
                mma16816(acc[mf][0], af[mf], &bf[0][0]);
                mma16816(acc[mf][1], af[mf], &bf[0][2]);
                mma16816(acc[mf][2], af[mf], &bf[1][0]);
                mma16816(acc[mf][3], af[mf], &bf[1][2]);
            }
        }
        __syncthreads();
    }

    const int colBase = n0 + wn * 32 + 2 * (lane & 3);
    float2 b2[4];
    #pragma unroll
    for (int nf = 0; nf < 4; nf++)
        b2[nf] = *(const float2*)(bias + colBase + nf * 8);

    const int rowBase = m0 + wm * 64 + (lane >> 2);
    #pragma unroll
    for (int mf = 0; mf < 4; mf++) {
        const int r0 = rowBase + mf * 16;
        #pragma unroll
        for (int nf = 0; nf < 4; nf++) {
            const int col = colBase + nf * 8;
            float2 v0 = make_float2(acc[mf][nf][0] + b2[nf].x,
                                    acc[mf][nf][1] + b2[nf].y);
            float2 v1 = make_float2(acc[mf][nf][2] + b2[nf].x,
                                    acc[mf][nf][3] + b2[nf].y);
            *(float2*)(C + (size_t)r0 * Nn + col)       = v0;
            *(float2*)(C + (size_t)(r0 + 8) * Nn + col) = v1;
        }
    }
}

// ---------------------------------------------------------------------------
// Fused attention kernel (fp32): grid (NWIN, NHEAD), 128 threads.
// 4-way ILP in QK dot products and softmax reductions.
// ---------------------------------------------------------------------------
__global__ __launch_bounds__(128)
void attn_kernel(const float* __restrict__ mask)
{
    __shared__ float q_s[NTOK][36];
    __shared__ float k_s[NTOK][36];
    __shared__ float v_s[NTOK][36];
    __shared__ float S[NTOK][53];   // S[j][i]

    const int w   = blockIdx.x;
    const int h   = blockIdx.y;
    const int tid = threadIdx.x;

    // qkv tile load, float4-wide (49 rows x 8 float4 per tensor)
    const size_t base0 = (size_t)w * NTOK * QKV_COLS + h * HEADD;
    for (int idx = tid; idx < NTOK * 8; idx += 128) {
        const int i = idx >> 3, c4 = idx & 7;
        const float* gp = g_qkv + base0 + (size_t)i * QKV_COLS + c4 * 4;
        float4 qv = *(const float4*)(gp);
        float4 kv = *(const float4*)(gp + 384);
        float4 vv = *(const float4*)(gp + 768);
        qv.x *= SCALE_F; qv.y *= SCALE_F; qv.z *= SCALE_F; qv.w *= SCALE_F;
        *(float4*)&q_s[i][c4 * 4] = qv;
        *(float4*)&k_s[i][c4 * 4] = kv;
        *(float4*)&v_s[i][c4 * 4] = vv;
    }

    const float* mrow = mask + (size_t)(w & (NW_IMG - 1)) * (NTOK * NTOK);
    const float* brow = g_bias + h * (NTOK * NTOK);
    for (int idx = tid; idx < NTOK * NTOK; idx += 128) {
        const int i = idx / NTOK;
        const int j = idx - i * NTOK;
        S[j][i] = brow[idx] + mrow[idx];
    }
    __syncthreads();

    // ---- Scores: S[j][i] += q_i . k_j  (4 independent partials) ----
    {
        const int j  = tid & 63;
        const int ig = tid >> 6;
        if (j < NTOK) {
            float kreg[HEADD];
            #pragma unroll
            for (int kq = 0; kq < 8; ++kq)
                *(float4*)&kreg[kq * 4] = *(const float4*)&k_s[j][kq * 4];
            const int i0 = ig ? 25 : 0;
            const int i1 = ig ? NTOK : 25;
            for (int i = i0; i < i1; ++i) {
                float a0 = 0.0f, a1 = 0.0f, a2 = 0.0f, a3 = 0.0f;
                #pragma unroll
                for (int kq = 0; kq < 8; ++kq) {
                    const float4 q4 = *(const float4*)&q_s[i][kq * 4];
                    a0 = fmaf(q4.x, kreg[kq * 4 + 0], a0);
                    a1 = fmaf(q4.y, kreg[kq * 4 + 1], a1);
                    a2 = fmaf(q4.z, kreg[kq * 4 + 2], a2);
                    a3 = fmaf(q4.w, kreg[kq * 4 + 3], a3);
                }
                S[j][i] += (a0 + a1) + (a2 + a3);
            }
        }
    }
    __syncthreads();

    // ---- Softmax over j for row i (4-way strided partials) ----
    if (tid < NTOK) {
        const int i = tid;
        float m0 = -1e30f, m1 = -1e30f, m2 = -1e30f, m3 = -1e30f;
        int j = 0;
        for (; j + 4 <= NTOK; j += 4) {
            m0 = fmaxf(m0, S[j + 0][i]);
            m1 = fmaxf(m1, S[j + 1][i]);
            m2 = fmaxf(m2, S[j + 2][i]);
            m3 = fmaxf(m3, S[j + 3][i]);
        }
        for (; j < NTOK; ++j) m0 = fmaxf(m0, S[j][i]);
        const float m = fmaxf(fmaxf(m0, m1), fmaxf(m2, m3));

        float s0 = 0.0f, s1 = 0.0f, s2 = 0.0f, s3 = 0.0f;
        j = 0;
        for (; j + 4 <= NTOK; j += 4) {
            float e0 = fast_exp(S[j + 0][i] - m);
            float e1 = fast_exp(S[j + 1][i] - m);
            float e2 = fast_exp(S[j + 2][i] - m);
            float e3 = fast_exp(S[j + 3][i] - m);
            S[j + 0][i] = e0; S[j + 1][i] = e1;
            S[j + 2][i] = e2; S[j + 3][i] = e3;
            s0 += e0; s1 += e1; s2 += e2; s3 += e3;
        }
        for (; j < NTOK; ++j) {
            float e = fast_exp(S[j][i] - m);
            S[j][i] = e;
            s0 += e;
        }
        const float inv = 1.0f / ((s0 + s1) + (s2 + s3));
        for (j = 0; j < NTOK; ++j) S[j][i] *= inv;
    }
    __syncthreads();

    // ---- O[i][d] = sum_j S[j][i] * v[j][d] ----
    {
        const int d  = tid & 31;
        const int ig = tid >> 5;
        const int i0 = ig * 13;
        const int nrows = (i0 + 13 <= NTOK) ? 13 : (NTOK - i0);
        float o[13];
        #pragma unroll
        for (int r = 0; r < 13; ++r) o[r] = 0.0f;

        for (int j = 0; j < NTOK; ++j) {
            const float vj = v_s[j][d];
            #pragma unroll
            for (int r = 0; r < 13; ++r)
                if (r < nrows) o[r] += S[j][i0 + r] * vj;
        }
        for (int r = 0; r < nrows; ++r) {
            const size_t rowg = (size_t)(w * NTOK + i0 + r);
            const size_t base = rowg * K2 + h * HEADD + d;
            const float val = o[r];
            const __half hi = __float2half_rn(val);
            const __half lo = __float2half_rn(val - __half2float(hi));
            g_attn2[base]       = hi;
            g_attn2[base + DIM] = lo;
        }
    }
}

// ---------------------------------------------------------------------------
// Launch
// ---------------------------------------------------------------------------
extern "C" void kernel_launch(void* const* d_in, const int* in_sizes, int n_in,
                              void* d_out, int out_size)
{
    const float* x         = (const float*)d_in[0];
    const float* mask      = (const float*)d_in[1];
    const float* rel_table = (const float*)d_in[2];
    const float* qkv_w     = (const float*)d_in[3];
    const float* qkv_b     = (const float*)d_in[4];
    const float* proj_w    = (const float*)d_in[5];
    const float* proj_b    = (const float*)d_in[6];
    const int*   rel_idx   = (const int*)d_in[7];
    float*       out       = (float*)d_out;

    void *qkv_p, *x2_p, *attn2_p, *wq2_p, *wp2_p;
    cudaGetSymbolAddress(&qkv_p,   g_qkv);
    cudaGetSymbolAddress(&x2_p,    g_x2);
    cudaGetSymbolAddress(&attn2_p, g_attn2);
    cudaGetSymbolAddress(&wq2_p,   g_wqkv2);
    cudaGetSymbolAddress(&wp2_p,   g_wproj2);

    cudaFuncSetAttribute(gemm_mma,
                         cudaFuncAttributeMaxDynamicSharedMemorySize, GSMEM);

    // Splits + bias precompute
    {
        long t4 = (long)MROWS * (DIM / 4);
        split_act_kernel<<<(unsigned)((t4 + 255) / 256), 256>>>(
            x, (__half*)x2_p, t4);
    }
    {
        long t4 = (long)QKV_COLS * (DIM / 4);
        split_wgt_kernel<<<(unsigned)((t4 + 255) / 256), 256>>>(
            qkv_w, (__half*)wq2_p, t4);
    }
    {
        long t4 = (long)DIM * (DIM / 4);
        split_wgt_kernel<<<(unsigned)((t4 + 255) / 256), 256>>>(
            proj_w, (__half*)wp2_p, t4);
    }
    {
        int tot = NHEAD * NTOK * NTOK;
        bias_prep_kernel<<<(tot + 255) / 256, 256>>>(rel_table, rel_idx);
    }

    // 1) QKV GEMM (HMMA fp16)
    {
        dim3 grid(QKV_COLS / 128, MROWS / 128);    // (9, 3136)
        gemm_mma<<<grid, 256, GSMEM>>>(
            (const __half*)x2_p, (const __half*)wq2_p,
            qkv_b, (float*)qkv_p, QKV_COLS);
    }

    // 2) Fused attention
    {
        dim3 grid(NWIN, NHEAD);
        attn_kernel<<<grid, 128>>>(mask);
    }

    // 3) Output projection GEMM (HMMA fp16)
    {
        dim3 grid(DIM / 128, MROWS / 128);         // (3, 3136)
        gemm_mma<<<grid, 256, GSMEM>>>(
            (const __half*)attn2_p, (const __half*)wp2_p,
            proj_b, out, DIM);
    }
}